// round 5
// baseline (speedup 1.0000x reference)
#include <cuda_runtime.h>
#include <cuda_bf16.h>
#include <cstdint>

// ---------------------------------------------------------------------------
// ResidualLogitAdapter — split pipeline for GB300 (sm_103)
//   Kernel A (prep):    W1/W2 -> bf16 transposed
//   Kernel B (copy):    out = z  (pure memcpy, max bandwidth)
//   Kernel C (compute): conf stats + MLP; writes out[in-domain] = z + dz
//                       directly (z values cached in smem from phase 1)
// ---------------------------------------------------------------------------

namespace {

constexpr int ROWS_PER_CTA = 128;
constexpr int THREADS      = 256;
constexpr int N_ROWS       = 131072;
constexpr int N_CTAS       = N_ROWS / ROWS_PER_CTA;   // 1024

constexpr int ZS_PITCH = 68;   // floats; 68 mod 32 = 4 -> conflict-free frag reads

// smem layout for compute kernel (bytes)
constexpr unsigned OFF_C     = 0;         // 128 * 4 floats (c0,c1,c2,pad)   2048
constexpr unsigned OFF_ALPHA = 2048;      // 128 floats                      512
constexpr unsigned OFF_DOM   = 2560;      // 128 ints (domain col offset)    512
constexpr unsigned OFF_B1V   = 3072;      // 128 floats (b1)                 512
constexpr unsigned OFF_W256  = 3584;      // 128 floats                      512
constexpr unsigned OFF_W257  = 4096;      // 128 floats                      512
constexpr unsigned OFF_W258  = 4608;      // 128 floats                      512
constexpr unsigned OFF_B2V   = 5120;      // 64 floats                       256
constexpr unsigned OFF_ZS    = 5376;      // 128 * 68 floats               34816
constexpr unsigned OFF_A1    = 40960;     // 4 chunks x [128 x 128B]       65536
constexpr unsigned OFF_B1    = 106496;    // 4 chunks x [128 x 128B]       65536
constexpr unsigned OFF_A2    = 172032;    // 2 chunks x [128 x 128B]       32768
constexpr unsigned OFF_B2    = 204800;    // 2 chunks x [ 64 x 128B]       16384
constexpr unsigned SMEM_TOTAL = 221184;

// Device-global scratch (no allocations allowed)
__device__ __nv_bfloat16 g_W1T[128 * 256];        // [h][f] = W1[f][h], f<256
__device__ __nv_bfloat16 g_W2T[64 * 128];         // [n][h] = W2[h][n]

__device__ __forceinline__ unsigned swz(unsigned o) { return o ^ ((o >> 3) & 0x70u); }

__device__ __forceinline__ void mma16816(float c[4], const unsigned a[4],
                                         unsigned b0, unsigned b1) {
    asm volatile(
        "mma.sync.aligned.m16n8k16.row.col.f32.bf16.bf16.f32 "
        "{%0,%1,%2,%3}, {%4,%5,%6,%7}, {%8,%9}, {%0,%1,%2,%3};"
        : "+f"(c[0]), "+f"(c[1]), "+f"(c[2]), "+f"(c[3])
        : "r"(a[0]), "r"(a[1]), "r"(a[2]), "r"(a[3]), "r"(b0), "r"(b1));
}

// ------------------------------ prep kernel --------------------------------

__global__ void prep_kernel(const float* __restrict__ W1, const float* __restrict__ W2) {
    int i = blockIdx.x * blockDim.x + threadIdx.x;
    if (i < 128 * 256) {
        int h = i >> 8, f = i & 255;
        g_W1T[i] = __float2bfloat16(W1[f * 128 + h]);
    }
    int i2 = i - 128 * 256;
    if (i2 >= 0 && i2 < 64 * 128) {
        int n = i2 >> 7, h = i2 & 127;
        g_W2T[i2] = __float2bfloat16(W2[h * 64 + n]);
    }
}

// ------------------------------ copy kernel --------------------------------
// Pure memcpy out = z.  4 float4 per thread.  grid = 16384.

__global__ void __launch_bounds__(256)
copy_kernel(const float4* __restrict__ z4, float4* __restrict__ out4) {
    const size_t base = ((size_t)blockIdx.x * 256u + threadIdx.x) * 4u;
    float4 v0 = z4[base + 0];
    float4 v1 = z4[base + 1];
    float4 v2 = z4[base + 2];
    float4 v3 = z4[base + 3];
    out4[base + 0] = v0;
    out4[base + 1] = v1;
    out4[base + 2] = v2;
    out4[base + 3] = v3;
}

// ----------------------------- compute kernel ------------------------------

__global__ void __launch_bounds__(THREADS, 1)
compute_kernel(const float* __restrict__ z, const float* __restrict__ feats,
               const float* __restrict__ W1, const float* __restrict__ b1,
               const float* __restrict__ b2, const float* __restrict__ alphas,
               const int* __restrict__ dom, float* __restrict__ out) {
    extern __shared__ char smem[];
    const int tid = threadIdx.x;
    const int wid = tid >> 5;
    const int lid = tid & 31;
    const int gid = lid >> 2;    // mma group id (0..7)
    const int tid4 = lid & 3;    // mma thread-in-group (0..3)
    const int row0 = blockIdx.x * ROWS_PER_CTA;

    float* cS     = (float*)(smem + OFF_C);
    float* alphaS = (float*)(smem + OFF_ALPHA);
    int*   domS   = (int*)(smem + OFF_DOM);
    float* b1S    = (float*)(smem + OFF_B1V);
    float* w256S  = (float*)(smem + OFF_W256);
    float* w257S  = (float*)(smem + OFF_W257);
    float* w258S  = (float*)(smem + OFF_W258);
    float* b2S    = (float*)(smem + OFF_B2V);
    float* zS     = (float*)(smem + OFF_ZS);

    // ---- Phase 0: prefetch ALL z-gather values for this warp's 16 rows
    //      (32 LDG in flight) so their latency hides under phase-2 streaming.
    const int rbase = wid * 16;
    float x0[16], x1[16];
    int offr[16];
    {
#pragma unroll
        for (int i = 0; i < 16; i++) {
            const int grow = row0 + rbase + i;
            offr[i] = dom[grow] * 64;                // warp-uniform
            const float* zr = z + (size_t)grow * 512 + offr[i];
            x0[i] = zr[lid];
            x1[i] = zr[lid + 32];
        }
    }

    // ---- Phase 2 (moved up): stage A1 (feats->bf16), B1 (W1^T), B2 (W2^T);
    //      128B-pitch SW128-swizzled chunks (uint2 = 4 bf16 = 8 bytes).
    {
        const float4* fv = (const float4*)feats + (size_t)row0 * 64;
#pragma unroll 4
        for (int j = tid; j < 128 * 64; j += THREADS) {    // groups of 4 floats
            int r = j >> 6, k4 = j & 63;
            float4 v = fv[(size_t)r * 64 + k4];
            unsigned chunk = (unsigned)(k4 >> 4);
            unsigned kb = (unsigned)((k4 & 15) << 3);
            __nv_bfloat162 p0 = __floats2bfloat162_rn(v.x, v.y);
            __nv_bfloat162 p1 = __floats2bfloat162_rn(v.z, v.w);
            uint2 u;
            u.x = *(unsigned*)&p0; u.y = *(unsigned*)&p1;
            *(uint2*)(smem + OFF_A1 + chunk * 16384u + swz((unsigned)r * 128u + kb)) = u;
        }
        const uint2* w1t = (const uint2*)g_W1T;            // 4 bf16 per uint2
#pragma unroll 4
        for (int j = tid; j < 128 * 64; j += THREADS) {
            int hr = j >> 6, k4 = j & 63;
            uint2 u = w1t[j];
            unsigned chunk = (unsigned)(k4 >> 4);
            unsigned kb = (unsigned)((k4 & 15) << 3);
            *(uint2*)(smem + OFF_B1 + chunk * 16384u + swz((unsigned)hr * 128u + kb)) = u;
        }
        const uint2* w2t = (const uint2*)g_W2T;
        for (int j = tid; j < 64 * 32; j += THREADS) {
            int nr = j >> 5, k4 = j & 31;
            uint2 u = w2t[j];
            unsigned chunk = (unsigned)(k4 >> 4);
            unsigned kb = (unsigned)((k4 & 15) << 3);
            *(uint2*)(smem + OFF_B2 + chunk * 8192u + swz((unsigned)nr * 128u + kb)) = u;
        }
        if (tid < 128) {
            b1S[tid]   = b1[tid];
            w256S[tid] = W1[256 * 128 + tid];
            w257S[tid] = W1[257 * 128 + tid];
            w258S[tid] = W1[258 * 128 + tid];
            if (tid < 64) b2S[tid] = b2[tid];
        }
    }

    // ---- Phase 1: softmax confidence stats on prefetched registers;
    //      also park z values in zS for the epilogue's fused output write.
    {
#pragma unroll
        for (int i = 0; i < 16; i++) {
            const int r = rbase + i;
            zS[r * ZS_PITCH + lid]      = x0[i];
            zS[r * ZS_PITCH + lid + 32] = x1[i];
            float m1 = fmaxf(x0[i], x1[i]);
            float m2 = fminf(x0[i], x1[i]);
#pragma unroll
            for (int s = 16; s > 0; s >>= 1) {
                float o1 = __shfl_xor_sync(0xffffffffu, m1, s);
                float o2 = __shfl_xor_sync(0xffffffffu, m2, s);
                float hi = fmaxf(m1, o1);
                float lo = fmaxf(fminf(m1, o1), fmaxf(m2, o2));
                m1 = hi; m2 = lo;
            }
            float e0 = expf(x0[i] - m1), e1 = expf(x1[i] - m1);
            float S = e0 + e1;
            float T = e0 * (x0[i] - m1) + e1 * (x1[i] - m1);
#pragma unroll
            for (int s = 16; s > 0; s >>= 1) {
                S += __shfl_xor_sync(0xffffffffu, S, s);
                T += __shfl_xor_sync(0xffffffffu, T, s);
            }
            if (lid == 0) {
                float inv = 1.0f / S;
                cS[r * 4 + 0] = inv;                          // p_max
                cS[r * 4 + 1] = logf(S) - T * inv;            // entropy
                cS[r * 4 + 2] = (1.0f - expf(m2 - m1)) * inv; // margin
                alphaS[r] = alphas[offr[i] >> 6];
                domS[r]   = offr[i];
            }
        }
    }
    __syncthreads();

    // ---- Phase 3: GEMM1  h_pre[128,128] = feats_bf16[128,256] @ W1[:256]
    //      Warp w: rows (w&3)*32 .. +31, cols (w>>2)*64 .. +63
    const int mrow0 = (wid & 3) * 32;
    {
        const int ncol0 = (wid >> 2) * 64;
        float acc[2][8][4];
#pragma unroll
        for (int mi = 0; mi < 2; mi++)
#pragma unroll
            for (int ni = 0; ni < 8; ni++)
#pragma unroll
                for (int q = 0; q < 4; q++) acc[mi][ni][q] = 0.0f;

#pragma unroll
        for (int kc = 0; kc < 4; kc++) {
            const char* aC = smem + OFF_A1 + kc * 16384u;
            const char* bC = smem + OFF_B1 + kc * 16384u;
#pragma unroll
            for (int ks = 0; ks < 4; ks++) {
                const unsigned kb = (unsigned)(ks * 32 + tid4 * 4);
                unsigned afr[2][4];
#pragma unroll
                for (int mi = 0; mi < 2; mi++) {
                    unsigned r = (unsigned)(mrow0 + mi * 16 + gid);
                    afr[mi][0] = *(const unsigned*)(aC + swz(r * 128u + kb));
                    afr[mi][1] = *(const unsigned*)(aC + swz((r + 8) * 128u + kb));
                    afr[mi][2] = *(const unsigned*)(aC + swz(r * 128u + kb + 16));
                    afr[mi][3] = *(const unsigned*)(aC + swz((r + 8) * 128u + kb + 16));
                }
#pragma unroll
                for (int ni = 0; ni < 8; ni++) {
                    unsigned n = (unsigned)(ncol0 + ni * 8 + gid);
                    unsigned bf0 = *(const unsigned*)(bC + swz(n * 128u + kb));
                    unsigned bf1 = *(const unsigned*)(bC + swz(n * 128u + kb + 16));
                    mma16816(acc[0][ni], afr[0], bf0, bf1);
                    mma16816(acc[1][ni], afr[1], bf0, bf1);
                }
            }
        }

        // ---- Phase 4: epilogue1 -> A2 = bf16(relu(h_pre + b1 + c @ W1[256:259]))
        const unsigned a2chunk = (unsigned)(wid >> 2) * 16384u;
#pragma unroll
        for (int mi = 0; mi < 2; mi++) {
            const int rA = mrow0 + mi * 16 + gid;      // rows rA and rA+8
            const float cA0 = cS[rA * 4 + 0], cA1 = cS[rA * 4 + 1], cA2 = cS[rA * 4 + 2];
            const float cB0 = cS[(rA + 8) * 4 + 0], cB1 = cS[(rA + 8) * 4 + 1],
                        cB2 = cS[(rA + 8) * 4 + 2];
#pragma unroll
            for (int ni = 0; ni < 8; ni++) {
                const int j = ncol0 + ni * 8 + tid4 * 2;    // global h col (even)
                const float bj0 = b1S[j],     bj1 = b1S[j + 1];
                const float wa0 = w256S[j],   wa1 = w256S[j + 1];
                const float wb0 = w257S[j],   wb1 = w257S[j + 1];
                const float wc0 = w258S[j],   wc1 = w258S[j + 1];
                float v0 = acc[mi][ni][0] + bj0 + cA0 * wa0 + cA1 * wb0 + cA2 * wc0;
                float v1 = acc[mi][ni][1] + bj1 + cA0 * wa1 + cA1 * wb1 + cA2 * wc1;
                float v2 = acc[mi][ni][2] + bj0 + cB0 * wa0 + cB1 * wb0 + cB2 * wc0;
                float v3 = acc[mi][ni][3] + bj1 + cB0 * wa1 + cB1 * wb1 + cB2 * wc1;
                v0 = fmaxf(v0, 0.0f); v1 = fmaxf(v1, 0.0f);
                v2 = fmaxf(v2, 0.0f); v3 = fmaxf(v3, 0.0f);
                __nv_bfloat162 pA = __floats2bfloat162_rn(v0, v1);
                __nv_bfloat162 pB = __floats2bfloat162_rn(v2, v3);
                const unsigned jb = (unsigned)((ni * 8 + tid4 * 2) * 2);  // byte col
                *(unsigned*)(smem + OFF_A2 + a2chunk +
                             swz((unsigned)rA * 128u + jb)) = *(unsigned*)&pA;
                *(unsigned*)(smem + OFF_A2 + a2chunk +
                             swz((unsigned)(rA + 8) * 128u + jb)) = *(unsigned*)&pB;
            }
        }
    }
    __syncthreads();

    // ---- Phase 5: GEMM2  dz[128,64] = h[128,128] @ W2
    //      Warp w: rows (w&3)*32, cols (w>>2)*32
    {
        const int ncol0 = (wid >> 2) * 32;
        float acc[2][4][4];
#pragma unroll
        for (int mi = 0; mi < 2; mi++)
#pragma unroll
            for (int ni = 0; ni < 4; ni++)
#pragma unroll
                for (int q = 0; q < 4; q++) acc[mi][ni][q] = 0.0f;

#pragma unroll
        for (int kc = 0; kc < 2; kc++) {
            const char* aC = smem + OFF_A2 + kc * 16384u;
            const char* bC = smem + OFF_B2 + kc * 8192u;
#pragma unroll
            for (int ks = 0; ks < 4; ks++) {
                const unsigned kb = (unsigned)(ks * 32 + tid4 * 4);
                unsigned afr[2][4];
#pragma unroll
                for (int mi = 0; mi < 2; mi++) {
                    unsigned r = (unsigned)(mrow0 + mi * 16 + gid);
                    afr[mi][0] = *(const unsigned*)(aC + swz(r * 128u + kb));
                    afr[mi][1] = *(const unsigned*)(aC + swz((r + 8) * 128u + kb));
                    afr[mi][2] = *(const unsigned*)(aC + swz(r * 128u + kb + 16));
                    afr[mi][3] = *(const unsigned*)(aC + swz((r + 8) * 128u + kb + 16));
                }
#pragma unroll
                for (int ni = 0; ni < 4; ni++) {
                    unsigned n = (unsigned)(ncol0 + ni * 8 + gid);
                    unsigned bf0 = *(const unsigned*)(bC + swz(n * 128u + kb));
                    unsigned bf1 = *(const unsigned*)(bC + swz(n * 128u + kb + 16));
                    mma16816(acc[0][ni], afr[0], bf0, bf1);
                    mma16816(acc[1][ni], afr[1], bf0, bf1);
                }
            }
        }

        // ---- Phase 6: epilogue2 -> write out[in-domain] = zS + dz directly.
        //      (copy kernel already wrote all other columns of these rows;
        //       this kernel runs after it, so these stores land last.)
#pragma unroll
        for (int mi = 0; mi < 2; mi++) {
            const int rA = mrow0 + mi * 16 + gid;
            const float alA = alphaS[rA];
            const float alB = alphaS[rA + 8];
            float* outA = out + (size_t)(row0 + rA) * 512 + domS[rA];
            float* outB = out + (size_t)(row0 + rA + 8) * 512 + domS[rA + 8];
            const float* zA = zS + rA * ZS_PITCH;
            const float* zB = zS + (rA + 8) * ZS_PITCH;
#pragma unroll
            for (int ni = 0; ni < 4; ni++) {
                const int j = ncol0 + ni * 8 + tid4 * 2;
                const float bj0 = b2S[j], bj1 = b2S[j + 1];
                float2 zvA = *(const float2*)(zA + j);
                float2 zvB = *(const float2*)(zB + j);
                float2 oA, oB;
                oA.x = zvA.x + (acc[mi][ni][0] + bj0) * alA;
                oA.y = zvA.y + (acc[mi][ni][1] + bj1) * alA;
                oB.x = zvB.x + (acc[mi][ni][2] + bj0) * alB;
                oB.y = zvB.y + (acc[mi][ni][3] + bj1) * alB;
                *(float2*)(outA + j) = oA;
                *(float2*)(outB + j) = oB;
            }
        }
    }
}

}  // namespace

// ------------------------------ launch -------------------------------------

extern "C" void kernel_launch(void* const* d_in, const int* in_sizes, int n_in,
                              void* d_out, int out_size) {
    const float* z      = (const float*)d_in[0];
    const float* feats  = (const float*)d_in[1];
    const float* W1     = (const float*)d_in[2];
    const float* b1     = (const float*)d_in[3];
    const float* W2     = (const float*)d_in[4];
    const float* b2     = (const float*)d_in[5];
    const float* alphas = (const float*)d_in[6];
    const int*   dom    = (const int*)d_in[7];
    float* out = (float*)d_out;

    cudaFuncSetAttribute(compute_kernel, cudaFuncAttributeMaxDynamicSharedMemorySize,
                         SMEM_TOTAL);

    prep_kernel<<<(128 * 256 + 64 * 128 + 255) / 256, 256>>>(W1, W2);
    copy_kernel<<<N_ROWS * 128 / (256 * 4), 256>>>((const float4*)z, (float4*)out);
    compute_kernel<<<N_CTAS, THREADS, SMEM_TOTAL>>>(z, feats, W1, b1, b2,
                                                    alphas, dom, out);
}

// round 6
// speedup vs baseline: 1.1538x; 1.1538x over previous
#include <cuda_runtime.h>
#include <cuda_bf16.h>
#include <cstdint>

// ---------------------------------------------------------------------------
// ResidualLogitAdapter — split pipeline for GB300 (sm_103)
//   Kernel A (prep):    W1/W2 -> bf16 transposed
//   Kernel B (copy):    out = z  (pure memcpy, max bandwidth)
//   Kernel C (compute): conf stats + MLP; writes out[in-domain] = z + dz.
//     2 CTAs/SM (smem 104KB, regs<=128): K-split GEMM1 through one 64KB
//     staging buffer pair; buffers reused for A2/B2 in GEMM2.
// ---------------------------------------------------------------------------

namespace {

constexpr int ROWS_PER_CTA = 128;
constexpr int THREADS      = 256;
constexpr int N_ROWS       = 131072;
constexpr int N_CTAS       = N_ROWS / ROWS_PER_CTA;   // 1024

constexpr int ZS_PITCH = 68;   // floats; 68 mod 32 = 4 -> conflict-free frag reads

// smem layout for compute kernel (bytes)
constexpr unsigned OFF_C     = 0;         // 128 * 4 floats                  2048
constexpr unsigned OFF_ALPHA = 2048;      // 128 floats                      512
constexpr unsigned OFF_DOM   = 2560;      // 128 ints                        512
constexpr unsigned OFF_B1V   = 3072;      // 128 floats (b1)                 512
constexpr unsigned OFF_W256  = 3584;      // 128 floats                      512
constexpr unsigned OFF_W257  = 4096;      // 128 floats                      512
constexpr unsigned OFF_W258  = 4608;      // 128 floats                      512
constexpr unsigned OFF_B2V   = 5120;      // 64 floats                       256
constexpr unsigned OFF_ZS    = 5376;      // 128 * 68 floats               34816
constexpr unsigned OFF_SHA   = 40960;     // 2 chunks x [128 x 128B]       32768
constexpr unsigned OFF_SHB   = 73728;     // 2 chunks x [128 x 128B]       32768
constexpr unsigned SMEM_TOTAL = 106496;   // 104 KB -> 2 CTAs/SM

// Device-global scratch (no allocations allowed)
__device__ __nv_bfloat16 g_W1T[128 * 256];        // [h][f] = W1[f][h], f<256
__device__ __nv_bfloat16 g_W2T[64 * 128];         // [n][h] = W2[h][n]

__device__ __forceinline__ unsigned swz(unsigned o) { return o ^ ((o >> 3) & 0x70u); }

__device__ __forceinline__ void mma16816(float c[4], const unsigned a[4],
                                         unsigned b0, unsigned b1) {
    asm volatile(
        "mma.sync.aligned.m16n8k16.row.col.f32.bf16.bf16.f32 "
        "{%0,%1,%2,%3}, {%4,%5,%6,%7}, {%8,%9}, {%0,%1,%2,%3};"
        : "+f"(c[0]), "+f"(c[1]), "+f"(c[2]), "+f"(c[3])
        : "r"(a[0]), "r"(a[1]), "r"(a[2]), "r"(a[3]), "r"(b0), "r"(b1));
}

// ------------------------------ prep kernel --------------------------------

__global__ void prep_kernel(const float* __restrict__ W1, const float* __restrict__ W2) {
    int i = blockIdx.x * blockDim.x + threadIdx.x;
    if (i < 128 * 256) {
        int h = i >> 8, f = i & 255;
        g_W1T[i] = __float2bfloat16(W1[f * 128 + h]);
    }
    int i2 = i - 128 * 256;
    if (i2 >= 0 && i2 < 64 * 128) {
        int n = i2 >> 7, h = i2 & 127;
        g_W2T[i2] = __float2bfloat16(W2[h * 64 + n]);
    }
}

// ------------------------------ copy kernel --------------------------------
// Pure memcpy out = z.  4 float4 per thread.  grid = 16384.

__global__ void __launch_bounds__(256)
copy_kernel(const float4* __restrict__ z4, float4* __restrict__ out4) {
    const size_t base = ((size_t)blockIdx.x * 256u + threadIdx.x) * 4u;
    float4 v0 = z4[base + 0];
    float4 v1 = z4[base + 1];
    float4 v2 = z4[base + 2];
    float4 v3 = z4[base + 3];
    out4[base + 0] = v0;
    out4[base + 1] = v1;
    out4[base + 2] = v2;
    out4[base + 3] = v3;
}

// ----------------------------- compute kernel ------------------------------

__global__ void __launch_bounds__(THREADS, 2)
compute_kernel(const float* __restrict__ z, const float* __restrict__ feats,
               const float* __restrict__ W1, const float* __restrict__ b1,
               const float* __restrict__ b2, const float* __restrict__ alphas,
               const int* __restrict__ dom, float* __restrict__ out) {
    extern __shared__ char smem[];
    const int tid = threadIdx.x;
    const int wid = tid >> 5;
    const int lid = tid & 31;
    const int gid = lid >> 2;    // mma group id (0..7)
    const int tid4 = lid & 3;    // mma thread-in-group (0..3)
    const int row0 = blockIdx.x * ROWS_PER_CTA;

    float* cS     = (float*)(smem + OFF_C);
    float* alphaS = (float*)(smem + OFF_ALPHA);
    int*   domS   = (int*)(smem + OFF_DOM);
    float* b1S    = (float*)(smem + OFF_B1V);
    float* w256S  = (float*)(smem + OFF_W256);
    float* w257S  = (float*)(smem + OFF_W257);
    float* w258S  = (float*)(smem + OFF_W258);
    float* b2S    = (float*)(smem + OFF_B2V);
    float* zS     = (float*)(smem + OFF_ZS);

    // ---- Phase 1: conf stats + zS.  16 rows/warp; all 32 z-gather LDG are
    //      batched up front; the sibling CTA (occ=2) hides the exposure.
    {
        const int rbase = wid * 16;
        float x0[16], x1[16];
        int offr[16];
#pragma unroll
        for (int i = 0; i < 16; i++) {
            const int grow = row0 + rbase + i;
            offr[i] = dom[grow] * 64;                // warp-uniform
            const float* zr = z + (size_t)grow * 512 + offr[i];
            x0[i] = zr[lid];
            x1[i] = zr[lid + 32];
        }
#pragma unroll
        for (int i = 0; i < 16; i++) {
            const int r = rbase + i;
            zS[r * ZS_PITCH + lid]      = x0[i];
            zS[r * ZS_PITCH + lid + 32] = x1[i];
            float m1 = fmaxf(x0[i], x1[i]);
            float m2 = fminf(x0[i], x1[i]);
#pragma unroll
            for (int s = 16; s > 0; s >>= 1) {
                float o1 = __shfl_xor_sync(0xffffffffu, m1, s);
                float o2 = __shfl_xor_sync(0xffffffffu, m2, s);
                float hi = fmaxf(m1, o1);
                float lo = fmaxf(fminf(m1, o1), fmaxf(m2, o2));
                m1 = hi; m2 = lo;
            }
            float e0 = expf(x0[i] - m1), e1 = expf(x1[i] - m1);
            float S = e0 + e1;
            float T = e0 * (x0[i] - m1) + e1 * (x1[i] - m1);
#pragma unroll
            for (int s = 16; s > 0; s >>= 1) {
                S += __shfl_xor_sync(0xffffffffu, S, s);
                T += __shfl_xor_sync(0xffffffffu, T, s);
            }
            if (lid == 0) {
                float inv = 1.0f / S;
                cS[r * 4 + 0] = inv;                          // p_max
                cS[r * 4 + 1] = logf(S) - T * inv;            // entropy
                cS[r * 4 + 2] = (1.0f - expf(m2 - m1)) * inv; // margin
                alphaS[r] = alphas[offr[i] >> 6];
                domS[r]   = offr[i];
            }
        }
        if (tid < 128) {
            b1S[tid]   = b1[tid];
            w256S[tid] = W1[256 * 128 + tid];
            w257S[tid] = W1[257 * 128 + tid];
            w258S[tid] = W1[258 * 128 + tid];
            if (tid < 64) b2S[tid] = b2[tid];
        }
    }

    // GEMM1 accumulators persist across both K-halves.
    const int mrow0 = (wid & 3) * 32;
    const int ncol0 = (wid >> 2) * 64;
    float acc[2][8][4];
#pragma unroll
    for (int mi = 0; mi < 2; mi++)
#pragma unroll
        for (int ni = 0; ni < 8; ni++)
#pragma unroll
            for (int q = 0; q < 4; q++) acc[mi][ni][q] = 0.0f;

    // ---- GEMM1 over two K-halves through one 64KB staging buffer pair.
#pragma unroll 1
    for (int half = 0; half < 2; half++) {
        // stage A-half (feats cols half*128..+127) and B-half (W1T same K)
        const float4* fv = (const float4*)feats + (size_t)row0 * 64 + half * 32;
#pragma unroll 4
        for (int j = tid; j < 128 * 32; j += THREADS) {   // 32 groups of 4 floats
            int r = j >> 5, k4 = j & 31;
            float4 v = fv[(size_t)r * 64 + k4];
            unsigned chunk = (unsigned)(k4 >> 4);
            unsigned kb = (unsigned)((k4 & 15) << 3);
            __nv_bfloat162 p0 = __floats2bfloat162_rn(v.x, v.y);
            __nv_bfloat162 p1 = __floats2bfloat162_rn(v.z, v.w);
            uint2 u;
            u.x = *(unsigned*)&p0; u.y = *(unsigned*)&p1;
            *(uint2*)(smem + OFF_SHA + chunk * 16384u + swz((unsigned)r * 128u + kb)) = u;
        }
        const uint2* w1t = (const uint2*)g_W1T + half * 32;   // 4 bf16 per uint2
#pragma unroll 4
        for (int j = tid; j < 128 * 32; j += THREADS) {
            int hr = j >> 5, k4 = j & 31;
            uint2 u = w1t[(size_t)hr * 64 + k4];
            unsigned chunk = (unsigned)(k4 >> 4);
            unsigned kb = (unsigned)((k4 & 15) << 3);
            *(uint2*)(smem + OFF_SHB + chunk * 16384u + swz((unsigned)hr * 128u + kb)) = u;
        }
        __syncthreads();

        // accumulate this K-half
#pragma unroll
        for (int kc = 0; kc < 2; kc++) {
            const char* aC = smem + OFF_SHA + kc * 16384u;
            const char* bC = smem + OFF_SHB + kc * 16384u;
#pragma unroll
            for (int ks = 0; ks < 4; ks++) {
                const unsigned kb = (unsigned)(ks * 32 + tid4 * 4);
                unsigned afr[2][4];
#pragma unroll
                for (int mi = 0; mi < 2; mi++) {
                    unsigned r = (unsigned)(mrow0 + mi * 16 + gid);
                    afr[mi][0] = *(const unsigned*)(aC + swz(r * 128u + kb));
                    afr[mi][1] = *(const unsigned*)(aC + swz((r + 8) * 128u + kb));
                    afr[mi][2] = *(const unsigned*)(aC + swz(r * 128u + kb + 16));
                    afr[mi][3] = *(const unsigned*)(aC + swz((r + 8) * 128u + kb + 16));
                }
#pragma unroll
                for (int ni = 0; ni < 8; ni++) {
                    unsigned n = (unsigned)(ncol0 + ni * 8 + gid);
                    unsigned bf0 = *(const unsigned*)(bC + swz(n * 128u + kb));
                    unsigned bf1 = *(const unsigned*)(bC + swz(n * 128u + kb + 16));
                    mma16816(acc[0][ni], afr[0], bf0, bf1);
                    mma16816(acc[1][ni], afr[1], bf0, bf1);
                }
            }
        }
        __syncthreads();   // done reading this half before restaging / reuse
    }

    // ---- Epilogue1: A2 = bf16(relu(h_pre + b1 + c @ W1[256:259])) -> SHA.
    //      Concurrently stage B2 (W2T, 16KB) -> SHB.
    {
#pragma unroll
        for (int mi = 0; mi < 2; mi++) {
            const int rA = mrow0 + mi * 16 + gid;      // rows rA and rA+8
            const float cA0 = cS[rA * 4 + 0], cA1 = cS[rA * 4 + 1], cA2 = cS[rA * 4 + 2];
            const float cB0 = cS[(rA + 8) * 4 + 0], cB1 = cS[(rA + 8) * 4 + 1],
                        cB2 = cS[(rA + 8) * 4 + 2];
#pragma unroll
            for (int ni = 0; ni < 8; ni++) {
                const int j = ncol0 + ni * 8 + tid4 * 2;    // global h col (even)
                const float bj0 = b1S[j],     bj1 = b1S[j + 1];
                const float wa0 = w256S[j],   wa1 = w256S[j + 1];
                const float wb0 = w257S[j],   wb1 = w257S[j + 1];
                const float wc0 = w258S[j],   wc1 = w258S[j + 1];
                float v0 = acc[mi][ni][0] + bj0 + cA0 * wa0 + cA1 * wb0 + cA2 * wc0;
                float v1 = acc[mi][ni][1] + bj1 + cA0 * wa1 + cA1 * wb1 + cA2 * wc1;
                float v2 = acc[mi][ni][2] + bj0 + cB0 * wa0 + cB1 * wb0 + cB2 * wc0;
                float v3 = acc[mi][ni][3] + bj1 + cB0 * wa1 + cB1 * wb1 + cB2 * wc1;
                v0 = fmaxf(v0, 0.0f); v1 = fmaxf(v1, 0.0f);
                v2 = fmaxf(v2, 0.0f); v3 = fmaxf(v3, 0.0f);
                __nv_bfloat162 pA = __floats2bfloat162_rn(v0, v1);
                __nv_bfloat162 pB = __floats2bfloat162_rn(v2, v3);
                // A2 chunk = h-col/64 = (wid>>2); byte col within chunk
                const unsigned a2chunk = (unsigned)(wid >> 2) * 16384u;
                const unsigned jb = (unsigned)((ni * 8 + tid4 * 2) * 2);
                *(unsigned*)(smem + OFF_SHA + a2chunk +
                             swz((unsigned)rA * 128u + jb)) = *(unsigned*)&pA;
                *(unsigned*)(smem + OFF_SHA + a2chunk +
                             swz((unsigned)(rA + 8) * 128u + jb)) = *(unsigned*)&pB;
            }
        }
        const uint2* w2t = (const uint2*)g_W2T;
        for (int j = tid; j < 64 * 32; j += THREADS) {
            int nr = j >> 5, k4 = j & 31;
            uint2 u = w2t[j];
            unsigned chunk = (unsigned)(k4 >> 4);
            unsigned kb = (unsigned)((k4 & 15) << 3);
            *(uint2*)(smem + OFF_SHB + chunk * 8192u + swz((unsigned)nr * 128u + kb)) = u;
        }
    }
    __syncthreads();

    // ---- GEMM2  dz[128,64] = h[128,128] @ W2;  warp cols (wid>>2)*32
    {
        const int ncol2 = (wid >> 2) * 32;
        float acc2[2][4][4];
#pragma unroll
        for (int mi = 0; mi < 2; mi++)
#pragma unroll
            for (int ni = 0; ni < 4; ni++)
#pragma unroll
                for (int q = 0; q < 4; q++) acc2[mi][ni][q] = 0.0f;

#pragma unroll
        for (int kc = 0; kc < 2; kc++) {
            const char* aC = smem + OFF_SHA + kc * 16384u;
            const char* bC = smem + OFF_SHB + kc * 8192u;
#pragma unroll
            for (int ks = 0; ks < 4; ks++) {
                const unsigned kb = (unsigned)(ks * 32 + tid4 * 4);
                unsigned afr[2][4];
#pragma unroll
                for (int mi = 0; mi < 2; mi++) {
                    unsigned r = (unsigned)(mrow0 + mi * 16 + gid);
                    afr[mi][0] = *(const unsigned*)(aC + swz(r * 128u + kb));
                    afr[mi][1] = *(const unsigned*)(aC + swz((r + 8) * 128u + kb));
                    afr[mi][2] = *(const unsigned*)(aC + swz(r * 128u + kb + 16));
                    afr[mi][3] = *(const unsigned*)(aC + swz((r + 8) * 128u + kb + 16));
                }
#pragma unroll
                for (int ni = 0; ni < 4; ni++) {
                    unsigned n = (unsigned)(ncol2 + ni * 8 + gid);
                    unsigned bf0 = *(const unsigned*)(bC + swz(n * 128u + kb));
                    unsigned bf1 = *(const unsigned*)(bC + swz(n * 128u + kb + 16));
                    mma16816(acc2[0][ni], afr[0], bf0, bf1);
                    mma16816(acc2[1][ni], afr[1], bf0, bf1);
                }
            }
        }

        // ---- Epilogue2: out[in-domain] = zS + (dz + b2) * alpha  (direct)
#pragma unroll
        for (int mi = 0; mi < 2; mi++) {
            const int rA = mrow0 + mi * 16 + gid;
            const float alA = alphaS[rA];
            const float alB = alphaS[rA + 8];
            float* outA = out + (size_t)(row0 + rA) * 512 + domS[rA];
            float* outB = out + (size_t)(row0 + rA + 8) * 512 + domS[rA + 8];
            const float* zA = zS + rA * ZS_PITCH;
            const float* zB = zS + (rA + 8) * ZS_PITCH;
#pragma unroll
            for (int ni = 0; ni < 4; ni++) {
                const int j = ncol2 + ni * 8 + tid4 * 2;
                const float bj0 = b2S[j], bj1 = b2S[j + 1];
                float2 zvA = *(const float2*)(zA + j);
                float2 zvB = *(const float2*)(zB + j);
                float2 oA, oB;
                oA.x = zvA.x + (acc2[mi][ni][0] + bj0) * alA;
                oA.y = zvA.y + (acc2[mi][ni][1] + bj1) * alA;
                oB.x = zvB.x + (acc2[mi][ni][2] + bj0) * alB;
                oB.y = zvB.y + (acc2[mi][ni][3] + bj1) * alB;
                *(float2*)(outA + j) = oA;
                *(float2*)(outB + j) = oB;
            }
        }
    }
}

}  // namespace

// ------------------------------ launch -------------------------------------

extern "C" void kernel_launch(void* const* d_in, const int* in_sizes, int n_in,
                              void* d_out, int out_size) {
    const float* z      = (const float*)d_in[0];
    const float* feats  = (const float*)d_in[1];
    const float* W1     = (const float*)d_in[2];
    const float* b1     = (const float*)d_in[3];
    const float* W2     = (const float*)d_in[4];
    const float* b2     = (const float*)d_in[5];
    const float* alphas = (const float*)d_in[6];
    const int*   dom    = (const int*)d_in[7];
    float* out = (float*)d_out;

    cudaFuncSetAttribute(compute_kernel, cudaFuncAttributeMaxDynamicSharedMemorySize,
                         SMEM_TOTAL);

    prep_kernel<<<(128 * 256 + 64 * 128 + 255) / 256, 256>>>(W1, W2);
    copy_kernel<<<N_ROWS * 128 / (256 * 4), 256>>>((const float4*)z, (float4*)out);
    compute_kernel<<<N_CTAS, THREADS, SMEM_TOTAL>>>(z, feats, W1, b1, b2,
                                                    alphas, dom, out);
}